// round 1
// baseline (speedup 1.0000x reference)
#include <cuda_runtime.h>
#include <cuda_bf16.h>

// Problem constants (fixed by the reference setup_inputs)
#define H_DIM   1024
#define L_CONV  20
#define M_TOTAL 16384           // B*S = 4*4096

// GEMM tiling
#define BM 128
#define BN 128
#define BK 8
#define TM 8
#define TN 8
// 256 threads per CTA: 16 (n) x 16 (m) micro-tile grid

// Scratch (allocation-free rule: __device__ globals)
__device__ float g_weff[H_DIM * H_DIM];           // 4 MB: mean of the 20 conv mats
__device__ float g_y[M_TOTAL * H_DIM];            // 64 MB: pre-norm GEMM output

// ---------------------------------------------------------------------------
// Kernel 1: W_eff[o,i] = (1/L) * sum_l conv_w[l, o, i]
// ---------------------------------------------------------------------------
__global__ __launch_bounds__(256) void reduce_w_kernel(const float* __restrict__ conv_w) {
    int idx = blockIdx.x * blockDim.x + threadIdx.x;   // 0 .. H*H-1
    float s = 0.0f;
    #pragma unroll
    for (int l = 0; l < L_CONV; l++) {
        s += conv_w[l * (H_DIM * H_DIM) + idx];
    }
    g_weff[idx] = s * (1.0f / (float)L_CONV);
}

// ---------------------------------------------------------------------------
// Kernel 2: y[m, n] = sum_k x[m, k] * W_eff[n, k]    (NT GEMM, fp32 FFMA)
// ---------------------------------------------------------------------------
__global__ __launch_bounds__(256) void gemm_kernel(const float* __restrict__ A) {
    __shared__ float As[BK][BM];
    __shared__ float Bs[BK][BN];

    const int tid = threadIdx.x;
    const int bm = blockIdx.y * BM;
    const int bn = blockIdx.x * BN;
    const int tx = tid & 15;   // n direction
    const int ty = tid >> 4;   // m direction

    // Global->shared loading map: 2 threads per 128-row tile row, float4 each
    const int lrow  = tid >> 1;          // 0..127
    const int lcol  = (tid & 1) * 4;     // 0 or 4

    const float* Aptr = A       + (size_t)(bm + lrow) * H_DIM + lcol;
    const float* Bptr = g_weff  + (size_t)(bn + lrow) * H_DIM + lcol;

    float acc[TM][TN];
    #pragma unroll
    for (int m = 0; m < TM; m++)
        #pragma unroll
        for (int n = 0; n < TN; n++)
            acc[m][n] = 0.0f;

    for (int k0 = 0; k0 < H_DIM; k0 += BK) {
        // Stage loads into registers while previous tile is still being consumed
        float4 av = *(const float4*)(Aptr + k0);
        float4 bv = *(const float4*)(Bptr + k0);

        __syncthreads();   // previous iteration's compute done before overwrite
        As[lcol + 0][lrow] = av.x;
        As[lcol + 1][lrow] = av.y;
        As[lcol + 2][lrow] = av.z;
        As[lcol + 3][lrow] = av.w;
        Bs[lcol + 0][lrow] = bv.x;
        Bs[lcol + 1][lrow] = bv.y;
        Bs[lcol + 2][lrow] = bv.z;
        Bs[lcol + 3][lrow] = bv.w;
        __syncthreads();

        #pragma unroll
        for (int kk = 0; kk < BK; kk++) {
            float a_frag[TM], b_frag[TN];
            #pragma unroll
            for (int m = 0; m < TM; m++) a_frag[m] = As[kk][ty * TM + m];
            #pragma unroll
            for (int n = 0; n < TN; n++) b_frag[n] = Bs[kk][tx * TN + n];
            #pragma unroll
            for (int m = 0; m < TM; m++)
                #pragma unroll
                for (int n = 0; n < TN; n++)
                    acc[m][n] = fmaf(a_frag[m], b_frag[n], acc[m][n]);
        }
    }

    // Write 8x8 microtile, vectorized float4 (TN=8 -> two float4 per row)
    #pragma unroll
    for (int m = 0; m < TM; m++) {
        float* crow = g_y + (size_t)(bm + ty * TM + m) * H_DIM + bn + tx * TN;
        float4 v0 = make_float4(acc[m][0], acc[m][1], acc[m][2], acc[m][3]);
        float4 v1 = make_float4(acc[m][4], acc[m][5], acc[m][6], acc[m][7]);
        ((float4*)crow)[0] = v0;
        ((float4*)crow)[1] = v1;
    }
}

// ---------------------------------------------------------------------------
// Kernel 3: RMSNorm over last dim (H=1024), one CTA (256 thr) per row.
// out = y * rsqrt(mean(y^2) + 1e-6) * norm_w
// ---------------------------------------------------------------------------
__global__ __launch_bounds__(256) void norm_kernel(const float* __restrict__ norm_w,
                                                   float* __restrict__ out) {
    const int row = blockIdx.x;
    const int tid = threadIdx.x;

    const float4* yrow = (const float4*)(g_y + (size_t)row * H_DIM);
    float4 v = yrow[tid];
    float ss = v.x * v.x + v.y * v.y + v.z * v.z + v.w * v.w;

    // warp reduce
    #pragma unroll
    for (int o = 16; o > 0; o >>= 1) ss += __shfl_xor_sync(0xFFFFFFFFu, ss, o);

    __shared__ float warp_s[8];
    if ((tid & 31) == 0) warp_s[tid >> 5] = ss;
    __syncthreads();

    __shared__ float total_s;
    if (tid < 8) {
        float t = warp_s[tid];
        #pragma unroll
        for (int o = 4; o > 0; o >>= 1) t += __shfl_xor_sync(0xFFu, t, o);
        if (tid == 0) total_s = t;
    }
    __syncthreads();

    float var = total_s * (1.0f / (float)H_DIM);
    float r = rsqrtf(var + 1e-6f);

    float4 w = ((const float4*)norm_w)[tid];
    float4 o4;
    o4.x = v.x * r * w.x;
    o4.y = v.y * r * w.y;
    o4.z = v.z * r * w.z;
    o4.w = v.w * r * w.w;
    ((float4*)(out + (size_t)row * H_DIM))[tid] = o4;
}

// ---------------------------------------------------------------------------
extern "C" void kernel_launch(void* const* d_in, const int* in_sizes, int n_in,
                              void* d_out, int out_size) {
    const float* x      = (const float*)d_in[0];   // [4, 4096, 1024]
    const float* conv_w = (const float*)d_in[1];   // [20, 1024, 1024]
    const float* norm_w = (const float*)d_in[2];   // [1024]
    float* out = (float*)d_out;                    // [4, 4096, 1024]

    // 1) weight reduction: H*H elements / 256
    reduce_w_kernel<<<(H_DIM * H_DIM) / 256, 256>>>(conv_w);

    // 2) GEMM: grid (N/BN, M/BM) = (8, 128)
    dim3 ggrid(H_DIM / BN, M_TOTAL / BM);
    gemm_kernel<<<ggrid, 256>>>(x);

    // 3) RMSNorm: one CTA per row
    norm_kernel<<<M_TOTAL, 256>>>(norm_w, out);
}

// round 7
// speedup vs baseline: 1.9709x; 1.9709x over previous
#include <cuda_runtime.h>
#include <cuda_bf16.h>
#include <cstdint>

// ---------------- problem constants ----------------
#define H_DIM   1024
#define L_CONV  20
#define M_TOTAL 16384           // B*S

// ---------------- GEMM tiling ----------------
#define BM 128
#define BN 128
#define KC 32                   // K per chunk (two k16 MMA steps)
#define NCHUNK (H_DIM / KC)     // 32
#define NSTAGE 3

// padded smem row: 32 data halves + 8 pad = 40 halves = 80 bytes
#define ROWH 40
#define MAT_BYTES (128 * ROWH * 2)          // 10240 B per matrix tile
#define A_HI_OFF 0
#define A_LO_OFF (1 * MAT_BYTES)
#define B_HI_OFF (2 * MAT_BYTES)
#define B_LO_OFF (3 * MAT_BYTES)
#define STAGE_BYTES (4 * MAT_BYTES)         // 40960
#define SMEM_BYTES (NSTAGE * STAGE_BYTES)   // 122880

// ---------------- scratch (__device__ globals; no allocs allowed) ----------------
__device__ __align__(128) __nv_bfloat16 g_ahi[(size_t)M_TOTAL * H_DIM];
__device__ __align__(128) __nv_bfloat16 g_alo[(size_t)M_TOTAL * H_DIM];
__device__ __align__(128) __nv_bfloat16 g_bhi[(size_t)H_DIM * H_DIM];
__device__ __align__(128) __nv_bfloat16 g_blo[(size_t)H_DIM * H_DIM];
__device__ __align__(128) float         g_y  [(size_t)M_TOTAL * H_DIM];

// ---------------- PTX helpers (all sm_80-era; safe for compute_103 PTX) ----------
__device__ __forceinline__ uint32_t smem_u32(const void* p) {
    uint32_t a;
    asm("{ .reg .u64 t; cvta.to.shared.u64 t, %1; cvt.u32.u64 %0, t; }" : "=r"(a) : "l"(p));
    return a;
}
__device__ __forceinline__ void cp16(uint32_t saddr, const void* g) {
    asm volatile("cp.async.cg.shared.global [%0], [%1], 16;\n" :: "r"(saddr), "l"(g) : "memory");
}
__device__ __forceinline__ void cp_commit() { asm volatile("cp.async.commit_group;" ::: "memory"); }
__device__ __forceinline__ void cp_wait1()  { asm volatile("cp.async.wait_group 1;" ::: "memory"); }

__device__ __forceinline__ void ldsm_x4(uint32_t& r0, uint32_t& r1, uint32_t& r2, uint32_t& r3,
                                        uint32_t addr) {
    asm volatile("ldmatrix.sync.aligned.m8n8.x4.shared.b16 {%0,%1,%2,%3}, [%4];"
                 : "=r"(r0), "=r"(r1), "=r"(r2), "=r"(r3) : "r"(addr));
}
__device__ __forceinline__ void mma16816(float c[4],
                                         uint32_t a0, uint32_t a1, uint32_t a2, uint32_t a3,
                                         uint32_t b0, uint32_t b1) {
    asm volatile("mma.sync.aligned.m16n8k16.row.col.f32.bf16.bf16.f32 "
                 "{%0,%1,%2,%3}, {%4,%5,%6,%7}, {%8,%9}, {%0,%1,%2,%3};"
                 : "+f"(c[0]), "+f"(c[1]), "+f"(c[2]), "+f"(c[3])
                 : "r"(a0), "r"(a1), "r"(a2), "r"(a3), "r"(b0), "r"(b1));
}

// ---------------------------------------------------------------------------
// Kernel 1: reduce conv_w over L (mean) and split into bf16 hi/lo
// ---------------------------------------------------------------------------
__global__ __launch_bounds__(256) void reduce_w_split_kernel(const float* __restrict__ conv_w) {
    int i4 = blockIdx.x * blockDim.x + threadIdx.x;        // float4 index, H*H/4
    float4 s = make_float4(0.f, 0.f, 0.f, 0.f);
    #pragma unroll
    for (int l = 0; l < L_CONV; l++) {
        float4 v = ((const float4*)conv_w)[(size_t)l * (H_DIM * H_DIM / 4) + i4];
        s.x += v.x; s.y += v.y; s.z += v.z; s.w += v.w;
    }
    const float inv = 1.0f / (float)L_CONV;
    float w[4] = { s.x * inv, s.y * inv, s.z * inv, s.w * inv };
    __nv_bfloat16 h[4], lo[4];
    #pragma unroll
    for (int j = 0; j < 4; j++) {
        h[j]  = __float2bfloat16_rn(w[j]);
        lo[j] = __float2bfloat16_rn(w[j] - __bfloat162float(h[j]));
    }
    ((__nv_bfloat162*)g_bhi)[2*i4]   = __nv_bfloat162(h[0],  h[1]);
    ((__nv_bfloat162*)g_bhi)[2*i4+1] = __nv_bfloat162(h[2],  h[3]);
    ((__nv_bfloat162*)g_blo)[2*i4]   = __nv_bfloat162(lo[0], lo[1]);
    ((__nv_bfloat162*)g_blo)[2*i4+1] = __nv_bfloat162(lo[2], lo[3]);
}

// ---------------------------------------------------------------------------
// Kernel 2: split x into bf16 hi/lo
// ---------------------------------------------------------------------------
__global__ __launch_bounds__(256) void split_x_kernel(const float* __restrict__ x) {
    size_t i4 = (size_t)blockIdx.x * blockDim.x + threadIdx.x;   // float4 index
    float4 v = ((const float4*)x)[i4];
    float w[4] = { v.x, v.y, v.z, v.w };
    __nv_bfloat16 h[4], lo[4];
    #pragma unroll
    for (int j = 0; j < 4; j++) {
        h[j]  = __float2bfloat16_rn(w[j]);
        lo[j] = __float2bfloat16_rn(w[j] - __bfloat162float(h[j]));
    }
    ((__nv_bfloat162*)g_ahi)[2*i4]   = __nv_bfloat162(h[0],  h[1]);
    ((__nv_bfloat162*)g_ahi)[2*i4+1] = __nv_bfloat162(h[2],  h[3]);
    ((__nv_bfloat162*)g_alo)[2*i4]   = __nv_bfloat162(lo[0], lo[1]);
    ((__nv_bfloat162*)g_alo)[2*i4+1] = __nv_bfloat162(lo[2], lo[3]);
}

// ---------------------------------------------------------------------------
// Kernel 3: HMMA (mma.sync bf16) GEMM, 3-term split, fp32 accumulate
//   y[m,n] = sum_k x[m,k] * Weff[n,k]
// CTA 128x128, 8 warps as 2(M) x 4(N), warp tile 64x32, KC=32, 3-stage cp.async
// ---------------------------------------------------------------------------
__device__ __forceinline__ void load_chunk(uint32_t st, int bm, int bn, int kc, int tid) {
    const size_t kbase = (size_t)kc * KC;
    #pragma unroll
    for (int i = 0; i < 2; i++) {
        int u = tid + i * 256;           // 0..511
        int row = u >> 2;                // 0..127
        int unit = u & 3;                // 4 x 16B per 64B row
        uint32_t soff = (uint32_t)(row * (ROWH * 2) + unit * 16);
        size_t ga = (size_t)(bm + row) * H_DIM + kbase + unit * 8;
        size_t gb = (size_t)(bn + row) * H_DIM + kbase + unit * 8;
        cp16(st + A_HI_OFF + soff, g_ahi + ga);
        cp16(st + A_LO_OFF + soff, g_alo + ga);
        cp16(st + B_HI_OFF + soff, g_bhi + gb);
        cp16(st + B_LO_OFF + soff, g_blo + gb);
    }
}

__global__ __launch_bounds__(256, 1) void gemm_hmma_kernel() {
    extern __shared__ __align__(128) char dynsm[];
    const uint32_t sm0 = smem_u32(dynsm);

    const int tid  = threadIdx.x;
    const int wid  = tid >> 5;
    const int lane = tid & 31;
    const int bm = blockIdx.y * BM;
    const int bn = blockIdx.x * BN;
    const int wm = (wid >> 2) * 64;      // warp M offset in CTA
    const int wn = (wid & 3) * 32;       // warp N offset in CTA

    // ldmatrix per-lane source row/col within a 16-wide tile
    const int lrow = (lane & 7) + ((lane >> 3) & 1) * 8;
    const int lcol = (lane >> 4) * 8;    // half (8 elements) selector

    float acc[4][4][4];                   // [mi][nj][frag]
    #pragma unroll
    for (int a = 0; a < 4; a++)
        #pragma unroll
        for (int b = 0; b < 4; b++)
            #pragma unroll
            for (int c = 0; c < 4; c++) acc[a][b][c] = 0.0f;

    // ---- prologue ----
    load_chunk(sm0 + 0 * STAGE_BYTES, bm, bn, 0, tid); cp_commit();
    load_chunk(sm0 + 1 * STAGE_BYTES, bm, bn, 1, tid); cp_commit();

    for (int c = 0; c < NCHUNK; c++) {
        cp_wait1();
        __syncthreads();                  // stage c resident for all warps
        const uint32_t st = sm0 + (uint32_t)(c % NSTAGE) * STAGE_BYTES;

        #pragma unroll
        for (int kk = 0; kk < 2; kk++) {
            uint32_t ah[4][4], al[4][4], bh[2][4], bl[2][4];
            #pragma unroll
            for (int mi = 0; mi < 4; mi++) {
                uint32_t off = (uint32_t)((wm + mi * 16 + lrow) * (ROWH * 2) +
                                          (kk * 16 + lcol) * 2);
                ldsm_x4(ah[mi][0], ah[mi][1], ah[mi][2], ah[mi][3], st + A_HI_OFF + off);
                ldsm_x4(al[mi][0], al[mi][1], al[mi][2], al[mi][3], st + A_LO_OFF + off);
            }
            #pragma unroll
            for (int j = 0; j < 2; j++) {
                uint32_t off = (uint32_t)((wn + j * 16 + lrow) * (ROWH * 2) +
                                          (kk * 16 + lcol) * 2);
                ldsm_x4(bh[j][0], bh[j][1], bh[j][2], bh[j][3], st + B_HI_OFF + off);
                ldsm_x4(bl[j][0], bl[j][1], bl[j][2], bl[j][3], st + B_LO_OFF + off);
            }
            #pragma unroll
            for (int mi = 0; mi < 4; mi++) {
                #pragma unroll
                for (int nj = 0; nj < 4; nj++) {
                    const int j2 = nj >> 1, sub = nj & 1;
                    uint32_t b0h = bh[j2][0 + sub], b1h = bh[j2][2 + sub];
                    uint32_t b0l = bl[j2][0 + sub], b1l = bl[j2][2 + sub];
                    mma16816(acc[mi][nj], ah[mi][0], ah[mi][1], ah[mi][2], ah[mi][3], b0h, b1h);
                    mma16816(acc[mi][nj], al[mi][0], al[mi][1], al[mi][2], al[mi][3], b0h, b1h);
                    mma16816(acc[mi][nj], ah[mi][0], ah[mi][1], ah[mi][2], ah[mi][3], b0l, b1l);
                }
            }
        }
        __syncthreads();                  // everyone done reading stage (c+2)%NSTAGE's slot
        if (c + 2 < NCHUNK)
            load_chunk(sm0 + (uint32_t)((c + 2) % NSTAGE) * STAGE_BYTES, bm, bn, c + 2, tid);
        cp_commit();                      // empty groups keep wait_group bookkeeping aligned
    }

    // ---- epilogue: direct stores (float2 per fragment pair) ----
    const int crow = lane >> 2;
    const int ccol = (lane & 3) * 2;
    #pragma unroll
    for (int mi = 0; mi < 4; mi++) {
        #pragma unroll
        for (int nj = 0; nj < 4; nj++) {
            size_t base = (size_t)(bm + wm + mi * 16 + crow) * H_DIM + (bn + wn + nj * 8 + ccol);
            *(float2*)(g_y + base)              = make_float2(acc[mi][nj][0], acc[mi][nj][1]);
            *(float2*)(g_y + base + 8 * H_DIM)  = make_float2(acc[mi][nj][2], acc[mi][nj][3]);
        }
    }
}

// ---------------------------------------------------------------------------
// Kernel 4: RMSNorm over last dim, one 256-thread CTA per row
// ---------------------------------------------------------------------------
__global__ __launch_bounds__(256) void norm_kernel(const float* __restrict__ norm_w,
                                                   float* __restrict__ out) {
    const int row = blockIdx.x;
    const int tid = threadIdx.x;

    const float4* yrow = (const float4*)(g_y + (size_t)row * H_DIM);
    float4 v = yrow[tid];
    float ss = v.x * v.x + v.y * v.y + v.z * v.z + v.w * v.w;

    #pragma unroll
    for (int o = 16; o > 0; o >>= 1) ss += __shfl_xor_sync(0xFFFFFFFFu, ss, o);

    __shared__ float warp_s[8];
    if ((tid & 31) == 0) warp_s[tid >> 5] = ss;
    __syncthreads();

    __shared__ float total_s;
    if (tid < 8) {
        float t = warp_s[tid];
        #pragma unroll
        for (int o = 4; o > 0; o >>= 1) t += __shfl_xor_sync(0xFFu, t, o);
        if (tid == 0) total_s = t;
    }
    __syncthreads();

    float r = rsqrtf(total_s * (1.0f / (float)H_DIM) + 1e-6f);
    float4 w = ((const float4*)norm_w)[tid];
    float4 o4 = make_float4(v.x * r * w.x, v.y * r * w.y, v.z * r * w.z, v.w * r * w.w);
    ((float4*)(out + (size_t)row * H_DIM))[tid] = o4;
}

// ---------------------------------------------------------------------------
extern "C" void kernel_launch(void* const* d_in, const int* in_sizes, int n_in,
                              void* d_out, int out_size) {
    const float* x      = (const float*)d_in[0];   // [4, 4096, 1024]
    const float* conv_w = (const float*)d_in[1];   // [20, 1024, 1024]
    const float* norm_w = (const float*)d_in[2];   // [1024]
    float* out = (float*)d_out;

    reduce_w_split_kernel<<<(H_DIM * H_DIM / 4) / 256, 256>>>(conv_w);
    split_x_kernel<<<(int)(((size_t)M_TOTAL * H_DIM / 4) / 256), 256>>>(x);

    cudaFuncSetAttribute(gemm_hmma_kernel,
                         cudaFuncAttributeMaxDynamicSharedMemorySize, SMEM_BYTES);
    dim3 ggrid(H_DIM / BN, M_TOTAL / BM);   // (8, 128)
    gemm_hmma_kernel<<<ggrid, 256, SMEM_BYTES>>>();

    norm_kernel<<<M_TOTAL, 256>>>(norm_w, out);
}

// round 8
// speedup vs baseline: 3.0343x; 1.5396x over previous
#include <cuda_runtime.h>
#include <cuda_fp16.h>
#include <cstdint>

// ---------------- problem constants ----------------
#define H_DIM   1024
#define L_CONV  20
#define M_TOTAL 16384           // B*S

// ---------------- GEMM tiling ----------------
#define BM 128
#define BN 128
#define KC 32                   // K per chunk (two k16 MMA steps)
#define NCHUNK (H_DIM / KC)     // 32
#define NSTAGE 3

// padded smem row: 32 data halves + 8 pad = 40 halves = 80 bytes
#define ROWH 40
#define MAT_BYTES (128 * ROWH * 2)          // 10240 B per matrix tile
#define A_OFF  0
#define BH_OFF (1 * MAT_BYTES)
#define BL_OFF (2 * MAT_BYTES)
#define STAGE_BYTES (3 * MAT_BYTES)         // 30720
#define SMEM_BYTES (NSTAGE * STAGE_BYTES)   // 92160 -> 2 CTAs/SM

// ---------------- scratch (__device__ globals; no allocs allowed) ----------------
__device__ __align__(128) __half g_xh[(size_t)M_TOTAL * H_DIM];   // 32 MB
__device__ __align__(128) __half g_wh[(size_t)H_DIM * H_DIM];     // 2 MB
__device__ __align__(128) __half g_wl[(size_t)H_DIM * H_DIM];     // 2 MB
__device__ __align__(128) float  g_y [(size_t)M_TOTAL * H_DIM];   // 64 MB

// ---------------- PTX helpers (all sm_80-era; safe for compute_103 PTX) ----------
__device__ __forceinline__ uint32_t smem_u32(const void* p) {
    uint32_t a;
    asm("{ .reg .u64 t; cvta.to.shared.u64 t, %1; cvt.u32.u64 %0, t; }" : "=r"(a) : "l"(p));
    return a;
}
__device__ __forceinline__ void cp16(uint32_t saddr, const void* g) {
    asm volatile("cp.async.cg.shared.global [%0], [%1], 16;\n" :: "r"(saddr), "l"(g) : "memory");
}
__device__ __forceinline__ void cp_commit() { asm volatile("cp.async.commit_group;" ::: "memory"); }
__device__ __forceinline__ void cp_wait1()  { asm volatile("cp.async.wait_group 1;" ::: "memory"); }

__device__ __forceinline__ void ldsm_x4(uint32_t& r0, uint32_t& r1, uint32_t& r2, uint32_t& r3,
                                        uint32_t addr) {
    asm volatile("ldmatrix.sync.aligned.m8n8.x4.shared.b16 {%0,%1,%2,%3}, [%4];"
                 : "=r"(r0), "=r"(r1), "=r"(r2), "=r"(r3) : "r"(addr));
}
__device__ __forceinline__ void mma16816(float c[4],
                                         uint32_t a0, uint32_t a1, uint32_t a2, uint32_t a3,
                                         uint32_t b0, uint32_t b1) {
    asm volatile("mma.sync.aligned.m16n8k16.row.col.f32.f16.f16.f32 "
                 "{%0,%1,%2,%3}, {%4,%5,%6,%7}, {%8,%9}, {%0,%1,%2,%3};"
                 : "+f"(c[0]), "+f"(c[1]), "+f"(c[2]), "+f"(c[3])
                 : "r"(a0), "r"(a1), "r"(a2), "r"(a3), "r"(b0), "r"(b1));
}

// ---------------------------------------------------------------------------
// Kernel 1: reduce conv_w over L (mean) and split into fp16 hi/lo
// ---------------------------------------------------------------------------
__global__ __launch_bounds__(256) void reduce_w_split_kernel(const float* __restrict__ conv_w) {
    int i4 = blockIdx.x * blockDim.x + threadIdx.x;        // float4 index, H*H/4
    float4 s = make_float4(0.f, 0.f, 0.f, 0.f);
    #pragma unroll
    for (int l = 0; l < L_CONV; l++) {
        float4 v = ((const float4*)conv_w)[(size_t)l * (H_DIM * H_DIM / 4) + i4];
        s.x += v.x; s.y += v.y; s.z += v.z; s.w += v.w;
    }
    const float inv = 1.0f / (float)L_CONV;
    float w[4] = { s.x * inv, s.y * inv, s.z * inv, s.w * inv };
    __half h[4], lo[4];
    #pragma unroll
    for (int j = 0; j < 4; j++) {
        h[j]  = __float2half_rn(w[j]);
        lo[j] = __float2half_rn(w[j] - __half2float(h[j]));
    }
    ((__half2*)g_wh)[2*i4]   = __half2(h[0],  h[1]);
    ((__half2*)g_wh)[2*i4+1] = __half2(h[2],  h[3]);
    ((__half2*)g_wl)[2*i4]   = __half2(lo[0], lo[1]);
    ((__half2*)g_wl)[2*i4+1] = __half2(lo[2], lo[3]);
}

// ---------------------------------------------------------------------------
// Kernel 2: x -> fp16 (single rounding; residual is the accepted 2e-4 error)
// ---------------------------------------------------------------------------
__global__ __launch_bounds__(256) void cvt_x_kernel(const float* __restrict__ x) {
    size_t i4 = (size_t)blockIdx.x * blockDim.x + threadIdx.x;   // float4 index
    float4 v = ((const float4*)x)[i4];
    __half2 a = __half2(__float2half_rn(v.x), __float2half_rn(v.y));
    __half2 b = __half2(__float2half_rn(v.z), __float2half_rn(v.w));
    ((__half2*)g_xh)[2*i4]   = a;
    ((__half2*)g_xh)[2*i4+1] = b;
}

// ---------------------------------------------------------------------------
// Kernel 3: HMMA fp16 GEMM, 2-term (xh*wh + xh*wl), fp32 accumulate
//   y[m,n] = sum_k xh[m,k] * (wh+wl)[n,k]
// CTA 128x128, 8 warps as 2(M) x 4(N), warp tile 64x32, KC=32, 3-stage cp.async
// ---------------------------------------------------------------------------
__device__ __forceinline__ void load_chunk(uint32_t st, int bm, int bn, int kc, int tid) {
    const size_t kbase = (size_t)kc * KC;
    #pragma unroll
    for (int i = 0; i < 2; i++) {
        int u = tid + i * 256;           // 0..511
        int row = u >> 2;                // 0..127
        int unit = u & 3;                // 4 x 16B per 64B row
        uint32_t soff = (uint32_t)(row * (ROWH * 2) + unit * 16);
        size_t ga = (size_t)(bm + row) * H_DIM + kbase + unit * 8;
        size_t gb = (size_t)(bn + row) * H_DIM + kbase + unit * 8;
        cp16(st + A_OFF  + soff, g_xh + ga);
        cp16(st + BH_OFF + soff, g_wh + gb);
        cp16(st + BL_OFF + soff, g_wl + gb);
    }
}

__global__ __launch_bounds__(256, 2) void gemm_hmma_kernel() {
    extern __shared__ __align__(128) char dynsm[];
    const uint32_t sm0 = smem_u32(dynsm);

    const int tid  = threadIdx.x;
    const int wid  = tid >> 5;
    const int lane = tid & 31;
    const int bm = blockIdx.y * BM;
    const int bn = blockIdx.x * BN;
    const int wm = (wid >> 2) * 64;      // warp M offset in CTA
    const int wn = (wid & 3) * 32;       // warp N offset in CTA

    // ldmatrix per-lane source row/col within a 16-wide tile
    const int lrow = (lane & 7) + ((lane >> 3) & 1) * 8;
    const int lcol = (lane >> 4) * 8;    // half (8 elements) selector

    float acc[4][4][4];                   // [mi][nj][frag]
    #pragma unroll
    for (int a = 0; a < 4; a++)
        #pragma unroll
        for (int b = 0; b < 4; b++)
            #pragma unroll
            for (int c = 0; c < 4; c++) acc[a][b][c] = 0.0f;

    // ---- prologue ----
    load_chunk(sm0 + 0 * STAGE_BYTES, bm, bn, 0, tid); cp_commit();
    load_chunk(sm0 + 1 * STAGE_BYTES, bm, bn, 1, tid); cp_commit();

    for (int c = 0; c < NCHUNK; c++) {
        cp_wait1();
        __syncthreads();                  // stage c resident for all warps
        const uint32_t st = sm0 + (uint32_t)(c % NSTAGE) * STAGE_BYTES;

        #pragma unroll
        for (int kk = 0; kk < 2; kk++) {
            uint32_t ah[4][4], bh[2][4], bl[2][4];
            #pragma unroll
            for (int mi = 0; mi < 4; mi++) {
                uint32_t off = (uint32_t)((wm + mi * 16 + lrow) * (ROWH * 2) +
                                          (kk * 16 + lcol) * 2);
                ldsm_x4(ah[mi][0], ah[mi][1], ah[mi][2], ah[mi][3], st + A_OFF + off);
            }
            #pragma unroll
            for (int j = 0; j < 2; j++) {
                uint32_t off = (uint32_t)((wn + j * 16 + lrow) * (ROWH * 2) +
                                          (kk * 16 + lcol) * 2);
                ldsm_x4(bh[j][0], bh[j][1], bh[j][2], bh[j][3], st + BH_OFF + off);
                ldsm_x4(bl[j][0], bl[j][1], bl[j][2], bl[j][3], st + BL_OFF + off);
            }
            #pragma unroll
            for (int mi = 0; mi < 4; mi++) {
                #pragma unroll
                for (int nj = 0; nj < 4; nj++) {
                    const int j2 = nj >> 1, sub = nj & 1;
                    mma16816(acc[mi][nj], ah[mi][0], ah[mi][1], ah[mi][2], ah[mi][3],
                             bh[j2][0 + sub], bh[j2][2 + sub]);
                    mma16816(acc[mi][nj], ah[mi][0], ah[mi][1], ah[mi][2], ah[mi][3],
                             bl[j2][0 + sub], bl[j2][2 + sub]);
                }
            }
        }
        __syncthreads();                  // everyone done reading the reused slot
        if (c + 2 < NCHUNK)
            load_chunk(sm0 + (uint32_t)((c + 2) % NSTAGE) * STAGE_BYTES, bm, bn, c + 2, tid);
        cp_commit();                      // empty groups keep wait_group bookkeeping aligned
    }

    // ---- epilogue: direct stores (float2 per fragment pair) ----
    const int crow = lane >> 2;
    const int ccol = (lane & 3) * 2;
    #pragma unroll
    for (int mi = 0; mi < 4; mi++) {
        #pragma unroll
        for (int nj = 0; nj < 4; nj++) {
            size_t base = (size_t)(bm + wm + mi * 16 + crow) * H_DIM + (bn + wn + nj * 8 + ccol);
            *(float2*)(g_y + base)              = make_float2(acc[mi][nj][0], acc[mi][nj][1]);
            *(float2*)(g_y + base + 8 * H_DIM)  = make_float2(acc[mi][nj][2], acc[mi][nj][3]);
        }
    }
}

// ---------------------------------------------------------------------------
// Kernel 4: RMSNorm over last dim, one 256-thread CTA per row
// ---------------------------------------------------------------------------
__global__ __launch_bounds__(256) void norm_kernel(const float* __restrict__ norm_w,
                                                   float* __restrict__ out) {
    const int row = blockIdx.x;
    const int tid = threadIdx.x;

    const float4* yrow = (const float4*)(g_y + (size_t)row * H_DIM);
    float4 v = yrow[tid];
    float ss = v.x * v.x + v.y * v.y + v.z * v.z + v.w * v.w;

    #pragma unroll
    for (int o = 16; o > 0; o >>= 1) ss += __shfl_xor_sync(0xFFFFFFFFu, ss, o);

    __shared__ float warp_s[8];
    if ((tid & 31) == 0) warp_s[tid >> 5] = ss;
    __syncthreads();

    __shared__ float total_s;
    if (tid < 8) {
        float t = warp_s[tid];
        #pragma unroll
        for (int o = 4; o > 0; o >>= 1) t += __shfl_xor_sync(0xFFu, t, o);
        if (tid == 0) total_s = t;
    }
    __syncthreads();

    float r = rsqrtf(total_s * (1.0f / (float)H_DIM) + 1e-6f);
    float4 w = ((const float4*)norm_w)[tid];
    float4 o4 = make_float4(v.x * r * w.x, v.y * r * w.y, v.z * r * w.z, v.w * r * w.w);
    ((float4*)(out + (size_t)row * H_DIM))[tid] = o4;
}

// ---------------------------------------------------------------------------
extern "C" void kernel_launch(void* const* d_in, const int* in_sizes, int n_in,
                              void* d_out, int out_size) {
    const float* x      = (const float*)d_in[0];   // [4, 4096, 1024]
    const float* conv_w = (const float*)d_in[1];   // [20, 1024, 1024]
    const float* norm_w = (const float*)d_in[2];   // [1024]
    float* out = (float*)d_out;

    reduce_w_split_kernel<<<(H_DIM * H_DIM / 4) / 256, 256>>>(conv_w);
    cvt_x_kernel<<<(int)(((size_t)M_TOTAL * H_DIM / 4) / 256), 256>>>(x);

    cudaFuncSetAttribute(gemm_hmma_kernel,
                         cudaFuncAttributeMaxDynamicSharedMemorySize, SMEM_BYTES);
    dim3 ggrid(H_DIM / BN, M_TOTAL / BM);   // (8, 128)
    gemm_hmma_kernel<<<ggrid, 256, SMEM_BYTES>>>();

    norm_kernel<<<M_TOTAL, 256>>>(norm_w, out);
}